// round 14
// baseline (speedup 1.0000x reference)
#include <cuda_runtime.h>
#include <cuda_fp16.h>
#include <mma.h>
#include <math.h>

using namespace nvcuda;

#define VV 4
#define NN 1536
#define DD 256
#define TOPK 32
#define NHEADS 4
#define HD 64
#define ROWS_TOT (VV*NN)   // 6144
#define CAP 256

// ---------------- scratch (device globals; no allocation allowed) ----------
__device__ __half g_Hh[VV*NN*DD];
__device__ __half g_ipwh[3*DD*DD];
__device__ __half g_owh[DD*DD];
__device__ __half g_WQh[VV*DD*DD];
__device__ __half g_WKh[VV*DD*DD];
__device__ __half g_WVh[VV*DD*DD];
__device__ __half g_qkvh[VV*NN*3*DD];
__device__ __half g_oh[VV*NN*DD];
__device__ __half g_alignedh[VV*NN*DD];
__device__ __half g_Qh[VV*NN*DD];
__device__ __half g_Kh[VV*NN*DD];
__device__ __half g_Vh[VV*NN*DD];
__device__ float  g_part[VV*8*DD];
__device__ float  g_vmean[VV*DD];
__device__ float  g_wts[ROWS_TOT*96];
__device__ int    g_topk[VV*VV*NN*TOPK];

// ---------------- fp32 -> fp16 converts -------------------------------------
__global__ void f2h(const float* __restrict__ in, __half* __restrict__ out, int n)
{
    int i = (blockIdx.x * 256 + threadIdx.x) * 8;
    if (i >= n) return;
    float4 a = *reinterpret_cast<const float4*>(in + i);
    float4 b = *reinterpret_cast<const float4*>(in + i + 4);
    __half2 h[4] = { __floats2half2_rn(a.x, a.y), __floats2half2_rn(a.z, a.w),
                     __floats2half2_rn(b.x, b.y), __floats2half2_rn(b.z, b.w) };
    *reinterpret_cast<uint4*>(out + i) = *reinterpret_cast<uint4*>(h);
}

__global__ void f2h_w(const float* __restrict__ i0, __half* __restrict__ o0, int n0,
                      const float* __restrict__ i1, __half* __restrict__ o1, int n1,
                      const float* __restrict__ i2, __half* __restrict__ o2, int n2,
                      const float* __restrict__ i3, __half* __restrict__ o3, int n3,
                      const float* __restrict__ i4, __half* __restrict__ o4, int n4)
{
    const float* in; __half* out; int n;
    switch (blockIdx.y) {
        case 0: in = i0; out = o0; n = n0; break;
        case 1: in = i1; out = o1; n = n1; break;
        case 2: in = i2; out = o2; n = n2; break;
        case 3: in = i3; out = o3; n = n3; break;
        default: in = i4; out = o4; n = n4; break;
    }
    int i = (blockIdx.x * 256 + threadIdx.x) * 8;
    if (i >= n) return;
    float4 a = *reinterpret_cast<const float4*>(in + i);
    float4 b = *reinterpret_cast<const float4*>(in + i + 4);
    __half2 h[4] = { __floats2half2_rn(a.x, a.y), __floats2half2_rn(a.z, a.w),
                     __floats2half2_rn(b.x, b.y), __floats2half2_rn(b.z, b.w) };
    *reinterpret_cast<uint4*>(out + i) = *reinterpret_cast<uint4*>(h);
}

// ---------------- cp.async helpers -----------------------------------------
__device__ __forceinline__ void cp16(void* smem, const void* gmem)
{
    unsigned s = (unsigned)__cvta_generic_to_shared(smem);
    asm volatile("cp.async.cg.shared.global [%0], [%1], 16;\n" :: "r"(s), "l"(gmem));
}
__device__ __forceinline__ void cp_commit()
{ asm volatile("cp.async.commit_group;\n"); }
template<int N> __device__ __forceinline__ void cp_wait()
{ asm volatile("cp.async.wait_group %0;\n" :: "n"(N)); }

// ---------------- tensor-core GEMM (round-12 config) ------------------------
#define LDA 40
#define LDS_ 20
#define KSTEPS (DD/32)
#define STAGES 4
#define HG_SMEM (STAGES*(64+128)*LDA*2)

template<int MODE>
__global__ __launch_bounds__(256, 2)
void hgemm(const __half* __restrict__ A0, const __half* __restrict__ W0,
           const __half* __restrict__ W1, const __half* __restrict__ W2,
           const float* __restrict__ bias,
           const float* __restrict__ Hx, const float* __restrict__ alphas,
           __half* __restrict__ outH, __half* __restrict__ outK,
           __half* __restrict__ outV, int Ncols)
{
    const int K = DD;
    const __half* A = A0;
    const __half* B = W0;
    long obase = 0;
    int which = 0;
    if (MODE == 2) {
        int z = blockIdx.z; which = z >> 2; int v = z & 3;
        A = A0 + (long)v * NN * DD;
        B = (which == 0 ? W0 : which == 1 ? W1 : W2) + (long)v * DD * DD;
        obase = (long)v * NN * DD;
    }

    extern __shared__ __align__(16) char gsm[];
    __half* As = reinterpret_cast<__half*>(gsm);
    __half* Bs = As + STAGES * 64 * LDA;
    float*  stage = reinterpret_cast<float*>(gsm);

    const int tid = threadIdx.x;
    const int w = tid >> 5, lane = tid & 31;
    const int wm = w >> 2, wn = w & 3;
    const int m0 = blockIdx.y * 64, n0 = blockIdx.x * 128;
    const int rowL = tid >> 2;
    const int ca   = tid & 3;

    wmma::fragment<wmma::accumulator, 16, 16, 16, float> cf[2][2];
#pragma unroll
    for (int i = 0; i < 2; i++)
#pragma unroll
        for (int j = 0; j < 2; j++) wmma::fill_fragment(cf[i][j], 0.f);

    auto issue = [&](int kt) {
        int s = kt & (STAGES - 1);
        int k0 = kt * 32;
        cp16(&As[(s*64 + rowL) * LDA + ca * 8],
             &A[(long)(m0 + rowL) * K + k0 + ca * 8]);
        cp16(&Bs[(s*128 + rowL) * LDA + ca * 8],
             &B[(long)(n0 + rowL) * K + k0 + ca * 8]);
        cp16(&Bs[(s*128 + rowL + 64) * LDA + ca * 8],
             &B[(long)(n0 + rowL + 64) * K + k0 + ca * 8]);
    };

    issue(0); cp_commit();
    issue(1); cp_commit();

    for (int kt = 0; kt < KSTEPS; kt++) {
        if (kt + 2 < KSTEPS) issue(kt + 2);
        cp_commit();
        cp_wait<2>();
        __syncthreads();

        const __half* Ab = &As[(kt & (STAGES-1)) * 64 * LDA];
        const __half* Bb = &Bs[(kt & (STAGES-1)) * 128 * LDA];
#pragma unroll
        for (int kk = 0; kk < 32; kk += 16) {
            wmma::fragment<wmma::matrix_a, 16, 16, 16, __half, wmma::row_major> af[2];
            wmma::fragment<wmma::matrix_b, 16, 16, 16, __half, wmma::col_major> bf[2];
#pragma unroll
            for (int i = 0; i < 2; i++)
                wmma::load_matrix_sync(af[i], &Ab[(wm*32 + i*16) * LDA + kk], LDA);
#pragma unroll
            for (int j = 0; j < 2; j++)
                wmma::load_matrix_sync(bf[j], &Bb[(wn*32 + j*16) * LDA + kk], LDA);
#pragma unroll
            for (int i = 0; i < 2; i++)
#pragma unroll
                for (int j = 0; j < 2; j++)
                    wmma::mma_sync(cf[i][j], af[i], bf[j], cf[i][j]);
        }
    }
    __syncthreads();

    const int erow = lane >> 1, ecol0 = (lane & 1) * 8;
    float* wstage = &stage[w * 16 * LDS_];
#pragma unroll
    for (int i = 0; i < 2; i++)
#pragma unroll
        for (int j = 0; j < 2; j++) {
            wmma::store_matrix_sync(wstage, cf[i][j], LDS_, wmma::mem_row_major);
            __syncwarp();
            int r = m0 + wm*32 + i*16 + erow;
            int c = n0 + wn*32 + j*16 + ecol0;
            const float* sp = &wstage[erow * LDS_ + ecol0];
            if (MODE == 0) {
                long off = (long)r * Ncols + c;
                __half2 h[4];
#pragma unroll
                for (int e = 0; e < 4; e++)
                    h[e] = __floats2half2_rn(sp[2*e]   + bias[c + 2*e],
                                             sp[2*e+1] + bias[c + 2*e+1]);
                *reinterpret_cast<uint4*>(outH + off) = *reinterpret_cast<uint4*>(h);
            } else if (MODE == 1) {
                float a = alphas[r / NN];
                long off = (long)r * DD + c;
                __half2 h[4];
#pragma unroll
                for (int e = 0; e < 4; e++) {
                    float v0 = a * (sp[2*e]   + bias[c + 2*e])   + (1.f - a) * Hx[off + 2*e];
                    float v1 = a * (sp[2*e+1] + bias[c + 2*e+1]) + (1.f - a) * Hx[off + 2*e+1];
                    h[e] = __floats2half2_rn(v0, v1);
                }
                *reinterpret_cast<uint4*>(outH + off) = *reinterpret_cast<uint4*>(h);
            } else {
                long off = obase + (long)r * DD + c;
                __half* dst = (which == 0) ? outH : (which == 1) ? outK : outV;
                __half2 h[4];
#pragma unroll
                for (int e = 0; e < 4; e++)
                    h[e] = __floats2half2_rn(sp[2*e], sp[2*e+1]);
                *reinterpret_cast<uint4*>(dst + off) = *reinterpret_cast<uint4*>(h);
            }
            __syncwarp();
        }
}

// ---------------- tiny attention over views: one warp per (n,h) ------------
__global__ __launch_bounds__(256)
void view_attn(const __half* __restrict__ qkv, __half* __restrict__ o)
{
    int gw = blockIdx.x * 8 + (threadIdx.x >> 5);
    if (gw >= NN * NHEADS) return;
    int lane = threadIdx.x & 31;
    int n = gw >> 2;
    int h = gw & 3;

    float2 qf[VV], kf[VV], vf[VV];
#pragma unroll
    for (int l = 0; l < VV; l++) {
        long base = ((long)(l * NN + n)) * (3 * DD) + h * HD + 2 * lane;
        qf[l] = __half22float2(*reinterpret_cast<const __half2*>(qkv + base));
        kf[l] = __half22float2(*reinterpret_cast<const __half2*>(qkv + base + DD));
        vf[l] = __half22float2(*reinterpret_cast<const __half2*>(qkv + base + 2*DD));
    }

    float s[VV][VV];
#pragma unroll
    for (int l = 0; l < VV; l++)
#pragma unroll
        for (int m = 0; m < VV; m++) {
            float p = qf[l].x*kf[m].x + qf[l].y*kf[m].y;
#pragma unroll
            for (int off = 16; off; off >>= 1)
                p += __shfl_xor_sync(0xFFFFFFFFu, p, off);
            s[l][m] = p * 0.125f;
        }

#pragma unroll
    for (int l = 0; l < VV; l++) {
        float mx = fmaxf(fmaxf(s[l][0], s[l][1]), fmaxf(s[l][2], s[l][3]));
        float e0 = __expf(s[l][0]-mx), e1 = __expf(s[l][1]-mx),
              e2 = __expf(s[l][2]-mx), e3 = __expf(s[l][3]-mx);
        float inv = 1.f / (e0+e1+e2+e3);
        float ox = (e0*vf[0].x + e1*vf[1].x + e2*vf[2].x + e3*vf[3].x) * inv;
        float oy = (e0*vf[0].y + e1*vf[1].y + e2*vf[2].y + e3*vf[3].y) * inv;
        long base = ((long)(l * NN + n)) * DD + h * HD + 2 * lane;
        *reinterpret_cast<__half2*>(o + base) = __floats2half2_rn(ox, oy);
    }
}

// ---------------- fast top-32 per off-diagonal (v,q,n) row of C -------------
__global__ __launch_bounds__(256)
void topk_fast(const float* __restrict__ C, int* __restrict__ outIdx)
{
    __shared__ unsigned long long buf[8][CAP];
    const unsigned FULL = 0xFFFFFFFFu;
    int wid = threadIdx.x >> 5, lane = threadIdx.x & 31;
    int gw = blockIdx.x * 8 + wid;
    int pair = gw / NN, n = gw - pair * NN;
    int v = pair / 3, r3 = pair - v * 3;
    int q = r3 + (r3 >= v ? 1 : 0);

    const float* row = C + ((long)(v*4 + q) * NN + n) * (long)NN;
    int* outp = outIdx + ((long)(v*4 + q) * NN + n) * TOPK;
    unsigned long long* wbuf = buf[wid];

    int cnt = 0;
    float thr = 0.95f;
#pragma unroll 1
    for (int att = 0; att < 2; att++) {
        cnt = 0;
#pragma unroll 1
        for (int i = lane; i < NN; i += 32) {
            float x = row[i];
            bool p = x > thr;
            unsigned m = __ballot_sync(FULL, p);
            if (p) {
                int pos = cnt + __popc(m & ((1u << lane) - 1u));
                if (pos < CAP)
                    wbuf[pos] = (((unsigned long long)__float_as_uint(x)) << 32)
                              | (unsigned)(0xFFFFFFFFu - i);
            }
            cnt += __popc(m);
        }
        if (cnt >= TOPK && cnt <= CAP) break;
        thr = 0.90f;
    }

    if (cnt < TOPK || cnt > CAP) {
        unsigned long long prev = 0xFFFFFFFFFFFFFFFFull;
        for (int j = 0; j < TOPK; j++) {
            unsigned long long best = 0;
            for (int i = lane; i < NN; i += 32) {
                unsigned b = __float_as_uint(row[i]);
                unsigned key32 = (b & 0x80000000u) ? ~b : (b | 0x80000000u);
                unsigned long long k =
                    (((unsigned long long)key32) << 32) | (unsigned)(0xFFFFFFFFu - i);
                if (k < prev && k > best) best = k;
            }
#pragma unroll
            for (int off = 16; off; off >>= 1) {
                unsigned long long o = __shfl_xor_sync(FULL, best, off);
                if (o > best) best = o;
            }
            if (lane == 0) outp[j] = (int)(0xFFFFFFFFu - (unsigned)best);
            prev = best;
        }
        return;
    }

    const int SL = CAP / 32;
    unsigned long long c[SL];
#pragma unroll
    for (int k = 0; k < SL; k++) {
        int j = lane + 32 * k;
        c[k] = (j < cnt) ? wbuf[j] : 0ull;
    }
    unsigned long long lmax = 0; int lslot = 0;
#pragma unroll
    for (int k = 0; k < SL; k++) if (c[k] > lmax) { lmax = c[k]; lslot = k; }

#pragma unroll 1
    for (int j = 0; j < TOPK; j++) {
        unsigned long long best = lmax;
#pragma unroll
        for (int off = 16; off; off >>= 1) {
            unsigned long long o = __shfl_xor_sync(FULL, best, off);
            if (o > best) best = o;
        }
        if (lmax == best && best != 0ull) {
            outp[j] = (int)(0xFFFFFFFFu - (unsigned)best);
            c[lslot] = 0ull;
            lmax = 0; lslot = 0;
#pragma unroll
            for (int k = 0; k < SL; k++) if (c[k] > lmax) { lmax = c[k]; lslot = k; }
        }
    }
}

// ---------------- Vn mean over tokens (p==q uniform-softmax term) ----------
__global__ void vmean_partial(const __half* __restrict__ Vh, float* __restrict__ part)
{
    int v = blockIdx.x, chunk = blockIdx.y, t = threadIdx.x;
    float s = 0.f;
    int nbeg = chunk * (NN/8), nend = nbeg + (NN/8);
    for (int n = nbeg; n < nend; n++)
        s += __half2float(Vh[((long)v * NN + n) * DD + t]);
    part[(v*8 + chunk) * DD + t] = s;
}
__global__ void vmean_final(const float* __restrict__ part, float* __restrict__ vmean)
{
    int v = blockIdx.x, t = threadIdx.x;
    float s = 0.f;
#pragma unroll
    for (int c = 0; c < 8; c++) s += part[(v*8 + c) * DD + t];
    vmean[v * DD + t] = s * (1.0f / NN);
}

// ---------------- nbr phase 1: 96 dots + 3 softmaxes -> weights -------------
// tiny smem (~2.5KB) => ~16 CTAs/SM of gather parallelism
__global__ __launch_bounds__(256)
void nbr_dots(const __half* __restrict__ Qh, const __half* __restrict__ Kh,
              const int* __restrict__ topk, float* __restrict__ wts)
{
    __shared__ float Qrow[DD];
    __shared__ float sdots[96];
    __shared__ int   srow[96];

    int pn = blockIdx.x;
    int p = pn / NN, n = pn % NN;
    int t = threadIdx.x, lane = t & 31, wid = t >> 5;

    Qrow[t] = __half2float(Qh[(long)pn * DD + t]);
    if (t < 96) {
        int view = t >> 5;
        int q = view + (view >= p ? 1 : 0);
        int idx = topk[(((long)(p*VV + q)) * NN + n) * TOPK + (t & 31)];
        srow[t] = q * NN + idx;
    }
    __syncthreads();

    float4 qa = *reinterpret_cast<const float4*>(&Qrow[lane*8]);
    float4 qb = *reinterpret_cast<const float4*>(&Qrow[lane*8+4]);
#pragma unroll
    for (int r = 0; r < 12; r += 6) {
        uint4 kv[6];
#pragma unroll
        for (int u = 0; u < 6; u++)
            kv[u] = *reinterpret_cast<const uint4*>(
                Kh + (long)srow[wid*12 + r + u] * DD + lane * 8);
#pragma unroll
        for (int u = 0; u < 6; u++) {
            float2 k0 = __half22float2(*reinterpret_cast<__half2*>(&kv[u].x));
            float2 k1 = __half22float2(*reinterpret_cast<__half2*>(&kv[u].y));
            float2 k2 = __half22float2(*reinterpret_cast<__half2*>(&kv[u].z));
            float2 k3 = __half22float2(*reinterpret_cast<__half2*>(&kv[u].w));
            float psum = qa.x*k0.x + qa.y*k0.y + qa.z*k1.x + qa.w*k1.y
                       + qb.x*k2.x + qb.y*k2.y + qb.z*k3.x + qb.w*k3.y;
#pragma unroll
            for (int off = 16; off; off >>= 1)
                psum += __shfl_xor_sync(0xFFFFFFFFu, psum, off);
            if (lane == 0) sdots[wid*12 + r + u] = psum * 0.0625f;
        }
    }
    __syncthreads();

    if (wid < 3) {
        float x = sdots[wid*32 + lane];
        float mx = x;
#pragma unroll
        for (int off = 16; off; off >>= 1)
            mx = fmaxf(mx, __shfl_xor_sync(0xFFFFFFFFu, mx, off));
        float e = __expf(x - mx);
        float sm = e;
#pragma unroll
        for (int off = 16; off; off >>= 1)
            sm += __shfl_xor_sync(0xFFFFFFFFu, sm, off);
        wts[(long)pn * 96 + wid*32 + lane] = e / sm;
    }
}

// ---------------- nbr phase 2: weighted V gather-sum + final fuse ----------
// tiny smem (~1KB) => high occupancy; V read straight from L2
__global__ __launch_bounds__(256)
void nbr_apply(const __half* __restrict__ Vh, const float* __restrict__ vmean,
               const int* __restrict__ topk, const float* __restrict__ wts,
               const __half* __restrict__ alignedh, const float* __restrict__ Hin,
               const float* __restrict__ alpha_align, const float* __restrict__ beta,
               float* __restrict__ out)
{
    __shared__ float sw[96];
    __shared__ int   srow[96];

    int pn = blockIdx.x;
    int p = pn / NN, n = pn % NN;
    int t = threadIdx.x;

    long rowOff = (long)pn * DD;
    float hin = Hin[rowOff + t];                       // prefetch (DRAM)
    float al  = __half2float(alignedh[rowOff + t]);    // prefetch (L2)
    float acc = vmean[p * DD + t];
    if (t < 96) {
        int view = t >> 5;
        int q = view + (view >= p ? 1 : 0);
        int idx = topk[(((long)(p*VV + q)) * NN + n) * TOPK + (t & 31)];
        srow[t] = q * NN + idx;
        sw[t]   = wts[(long)pn * 96 + t];
    }
    __syncthreads();

    float a1 = 0.f;
#pragma unroll 8
    for (int j = 0; j < 96; j += 2) {
        acc = fmaf(sw[j],   __half2float(Vh[(long)srow[j]   * DD + t]), acc);
        a1  = fmaf(sw[j+1], __half2float(Vh[(long)srow[j+1] * DD + t]), a1);
    }
    acc += a1;

    float aa = 1.f / (1.f + __expf(-alpha_align[0]));
    float bb = 1.f / (1.f + __expf(-beta[0]));
    float f  = fmaxf(aa * al + (1.f - aa) * acc, 0.f);
    out[rowOff + t] = bb * hin + (1.f - bb) * f;
}

// ---------------- launch ----------------------------------------------------
extern "C" void kernel_launch(void* const* d_in, const int* in_sizes, int n_in,
                              void* d_out, int out_size)
{
    const float* H      = (const float*)d_in[0];
    const float* C      = (const float*)d_in[1];
    const float* WQ     = (const float*)d_in[2];
    const float* WK     = (const float*)d_in[3];
    const float* WV     = (const float*)d_in[4];
    const float* ipw    = (const float*)d_in[5];
    const float* ipb    = (const float*)d_in[6];
    const float* ow     = (const float*)d_in[7];
    const float* ob     = (const float*)d_in[8];
    const float* alphas = (const float*)d_in[9];
    const float* aal    = (const float*)d_in[10];
    const float* bet    = (const float*)d_in[11];
    float* out = (float*)d_out;

    __half *p_Hh, *p_ipwh, *p_owh, *p_WQh, *p_WKh, *p_WVh;
    __half *p_qkvh, *p_oh, *p_alignedh, *p_Qh, *p_Kh, *p_Vh;
    float *p_part, *p_vmean, *p_wts;
    int* p_tk;
    cudaGetSymbolAddress((void**)&p_Hh, g_Hh);
    cudaGetSymbolAddress((void**)&p_ipwh, g_ipwh);
    cudaGetSymbolAddress((void**)&p_owh, g_owh);
    cudaGetSymbolAddress((void**)&p_WQh, g_WQh);
    cudaGetSymbolAddress((void**)&p_WKh, g_WKh);
    cudaGetSymbolAddress((void**)&p_WVh, g_WVh);
    cudaGetSymbolAddress((void**)&p_qkvh, g_qkvh);
    cudaGetSymbolAddress((void**)&p_oh, g_oh);
    cudaGetSymbolAddress((void**)&p_alignedh, g_alignedh);
    cudaGetSymbolAddress((void**)&p_Qh, g_Qh);
    cudaGetSymbolAddress((void**)&p_Kh, g_Kh);
    cudaGetSymbolAddress((void**)&p_Vh, g_Vh);
    cudaGetSymbolAddress((void**)&p_part, g_part);
    cudaGetSymbolAddress((void**)&p_vmean, g_vmean);
    cudaGetSymbolAddress((void**)&p_wts, g_wts);
    cudaGetSymbolAddress((void**)&p_tk, g_topk);

    static cudaStream_t sB = nullptr, sC = nullptr;
    static cudaEvent_t evRoot = nullptr, evB = nullptr, evC = nullptr;
    if (sB == nullptr) {
        cudaStreamCreateWithFlags(&sB, cudaStreamNonBlocking);
        cudaStreamCreateWithFlags(&sC, cudaStreamNonBlocking);
        cudaEventCreateWithFlags(&evRoot, cudaEventDisableTiming);
        cudaEventCreateWithFlags(&evB, cudaEventDisableTiming);
        cudaEventCreateWithFlags(&evC, cudaEventDisableTiming);
    }
    cudaFuncSetAttribute(hgemm<0>, cudaFuncAttributeMaxDynamicSharedMemorySize, HG_SMEM);
    cudaFuncSetAttribute(hgemm<1>, cudaFuncAttributeMaxDynamicSharedMemorySize, HG_SMEM);
    cudaFuncSetAttribute(hgemm<2>, cudaFuncAttributeMaxDynamicSharedMemorySize, HG_SMEM);

    auto cgrid = [](int n){ return (n/8 + 255) / 256; };

    // fork side streams
    cudaEventRecord(evRoot, 0);
    cudaStreamWaitEvent(sB, evRoot, 0);
    cudaStreamWaitEvent(sC, evRoot, 0);

    // side stream B: top-k over C
    topk_fast<<<(12 * NN) / 8, 256, 0, sB>>>(C, p_tk);
    cudaEventRecord(evB, sB);

    // side stream C: all weight conversions in ONE launch
    f2h_w<<<dim3(cgrid(VV*DD*DD), 5), 256, 0, sC>>>(
        ipw, p_ipwh, 3*DD*DD,
        ow,  p_owh,  DD*DD,
        WQ,  p_WQh,  VV*DD*DD,
        WK,  p_WKh,  VV*DD*DD,
        WV,  p_WVh,  VV*DD*DD);
    cudaEventRecord(evC, sC);

    // main chain
    f2h<<<cgrid(ROWS_TOT*DD), 256>>>(H, p_Hh, ROWS_TOT*DD);
    cudaStreamWaitEvent(0, evC, 0);

    // 1) qkv(f16) = H @ in_proj_w^T + b
    hgemm<0><<<dim3(768/128, ROWS_TOT/64), 256, HG_SMEM>>>(
        p_Hh, p_ipwh, nullptr, nullptr, ipb, nullptr, nullptr,
        p_qkvh, nullptr, nullptr, 3*DD);

    // 2) tiny 4x4 attention over views -> o (fp16)
    view_attn<<<(NN*NHEADS)/8, 256>>>(p_qkvh, p_oh);

    // 3) alignedh = half(a*(o @ out_w^T + b) + (1-a)*H)
    hgemm<1><<<dim3(DD/128, ROWS_TOT/64), 256, HG_SMEM>>>(
        p_oh, p_owh, nullptr, nullptr, ob, H, alphas,
        p_alignedh, nullptr, nullptr, DD);

    // 4) fused per-view Qh/Kh/Vh (all fp16)
    hgemm<2><<<dim3(DD/128, NN/64, 12), 256, HG_SMEM>>>(
        p_alignedh, p_WQh, p_WKh, p_WVh, nullptr, nullptr, nullptr,
        p_Qh, p_Kh, p_Vh, DD);

    // 5) mean of Vn over tokens
    vmean_partial<<<dim3(VV, 8), 256>>>(p_Vh, p_part);
    vmean_final<<<VV, 256>>>(p_part, p_vmean);

    cudaStreamWaitEvent(0, evB, 0);

    // 6) sparse neighbor attention: dots+softmax, then weighted gather + fuse
    nbr_dots<<<ROWS_TOT, 256>>>(p_Qh, p_Kh, p_tk, p_wts);
    nbr_apply<<<ROWS_TOT, 256>>>(p_Vh, p_vmean, p_tk, p_wts,
                                 p_alignedh, H, aal, bet, out);
}

// round 15
// speedup vs baseline: 1.0557x; 1.0557x over previous
#include <cuda_runtime.h>
#include <cuda_fp16.h>
#include <mma.h>
#include <math.h>

using namespace nvcuda;

#define VV 4
#define NN 1536
#define DD 256
#define TOPK 32
#define NHEADS 4
#define HD 64
#define ROWS_TOT (VV*NN)   // 6144
#define CAP 256

// ---------------- scratch (device globals; no allocation allowed) ----------
__device__ __half g_Hh[VV*NN*DD];
__device__ __half g_ipwh[3*DD*DD];
__device__ __half g_owh[DD*DD];
__device__ __half g_WQh[VV*DD*DD];
__device__ __half g_WKh[VV*DD*DD];
__device__ __half g_WVh[VV*DD*DD];
__device__ __half g_qkvh[VV*NN*3*DD];
__device__ __half g_oh[VV*NN*DD];
__device__ __half g_alignedh[VV*NN*DD];
__device__ __half g_Qh[VV*NN*DD];
__device__ __half g_Kh[VV*NN*DD];
__device__ __half g_Vh[VV*NN*DD];
__device__ float  g_part[VV*8*DD];
__device__ float  g_amean[VV*DD];
__device__ float  g_vmean[VV*DD];
__device__ int    g_topk[VV*VV*NN*TOPK];

// ---------------- fp32 -> fp16 converts -------------------------------------
__global__ void f2h(const float* __restrict__ in, __half* __restrict__ out, int n)
{
    int i = (blockIdx.x * 256 + threadIdx.x) * 8;
    if (i >= n) return;
    float4 a = *reinterpret_cast<const float4*>(in + i);
    float4 b = *reinterpret_cast<const float4*>(in + i + 4);
    __half2 h[4] = { __floats2half2_rn(a.x, a.y), __floats2half2_rn(a.z, a.w),
                     __floats2half2_rn(b.x, b.y), __floats2half2_rn(b.z, b.w) };
    *reinterpret_cast<uint4*>(out + i) = *reinterpret_cast<uint4*>(h);
}

__global__ void f2h_w(const float* __restrict__ i0, __half* __restrict__ o0, int n0,
                      const float* __restrict__ i1, __half* __restrict__ o1, int n1,
                      const float* __restrict__ i2, __half* __restrict__ o2, int n2,
                      const float* __restrict__ i3, __half* __restrict__ o3, int n3,
                      const float* __restrict__ i4, __half* __restrict__ o4, int n4)
{
    const float* in; __half* out; int n;
    switch (blockIdx.y) {
        case 0: in = i0; out = o0; n = n0; break;
        case 1: in = i1; out = o1; n = n1; break;
        case 2: in = i2; out = o2; n = n2; break;
        case 3: in = i3; out = o3; n = n3; break;
        default: in = i4; out = o4; n = n4; break;
    }
    int i = (blockIdx.x * 256 + threadIdx.x) * 8;
    if (i >= n) return;
    float4 a = *reinterpret_cast<const float4*>(in + i);
    float4 b = *reinterpret_cast<const float4*>(in + i + 4);
    __half2 h[4] = { __floats2half2_rn(a.x, a.y), __floats2half2_rn(a.z, a.w),
                     __floats2half2_rn(b.x, b.y), __floats2half2_rn(b.z, b.w) };
    *reinterpret_cast<uint4*>(out + i) = *reinterpret_cast<uint4*>(h);
}

// ---------------- cp.async helpers -----------------------------------------
__device__ __forceinline__ void cp16(void* smem, const void* gmem)
{
    unsigned s = (unsigned)__cvta_generic_to_shared(smem);
    asm volatile("cp.async.cg.shared.global [%0], [%1], 16;\n" :: "r"(s), "l"(gmem));
}
__device__ __forceinline__ void cp_commit()
{ asm volatile("cp.async.commit_group;\n"); }
template<int N> __device__ __forceinline__ void cp_wait()
{ asm volatile("cp.async.wait_group %0;\n" :: "n"(N)); }

// ---------------- tensor-core GEMM (round-12 config) ------------------------
#define LDA 40
#define LDS_ 20
#define KSTEPS (DD/32)
#define STAGES 4
#define HG_SMEM (STAGES*(64+128)*LDA*2)

template<int MODE>
__global__ __launch_bounds__(256, 2)
void hgemm(const __half* __restrict__ A0, const __half* __restrict__ W0,
           const __half* __restrict__ W1, const __half* __restrict__ W2,
           const float* __restrict__ bias,
           const float* __restrict__ Hx, const float* __restrict__ alphas,
           __half* __restrict__ outH, __half* __restrict__ outK,
           __half* __restrict__ outV, int Ncols)
{
    const int K = DD;
    const __half* A = A0;
    const __half* B = W0;
    long obase = 0;
    int which = 0;
    if (MODE == 2) {
        int z = blockIdx.z; which = z >> 2; int v = z & 3;
        A = A0 + (long)v * NN * DD;
        B = (which == 0 ? W0 : which == 1 ? W1 : W2) + (long)v * DD * DD;
        obase = (long)v * NN * DD;
    }

    extern __shared__ __align__(16) char gsm[];
    __half* As = reinterpret_cast<__half*>(gsm);
    __half* Bs = As + STAGES * 64 * LDA;
    float*  stage = reinterpret_cast<float*>(gsm);

    const int tid = threadIdx.x;
    const int w = tid >> 5, lane = tid & 31;
    const int wm = w >> 2, wn = w & 3;
    const int m0 = blockIdx.y * 64, n0 = blockIdx.x * 128;
    const int rowL = tid >> 2;
    const int ca   = tid & 3;

    wmma::fragment<wmma::accumulator, 16, 16, 16, float> cf[2][2];
#pragma unroll
    for (int i = 0; i < 2; i++)
#pragma unroll
        for (int j = 0; j < 2; j++) wmma::fill_fragment(cf[i][j], 0.f);

    auto issue = [&](int kt) {
        int s = kt & (STAGES - 1);
        int k0 = kt * 32;
        cp16(&As[(s*64 + rowL) * LDA + ca * 8],
             &A[(long)(m0 + rowL) * K + k0 + ca * 8]);
        cp16(&Bs[(s*128 + rowL) * LDA + ca * 8],
             &B[(long)(n0 + rowL) * K + k0 + ca * 8]);
        cp16(&Bs[(s*128 + rowL + 64) * LDA + ca * 8],
             &B[(long)(n0 + rowL + 64) * K + k0 + ca * 8]);
    };

    issue(0); cp_commit();
    issue(1); cp_commit();

    for (int kt = 0; kt < KSTEPS; kt++) {
        if (kt + 2 < KSTEPS) issue(kt + 2);
        cp_commit();
        cp_wait<2>();
        __syncthreads();

        const __half* Ab = &As[(kt & (STAGES-1)) * 64 * LDA];
        const __half* Bb = &Bs[(kt & (STAGES-1)) * 128 * LDA];
#pragma unroll
        for (int kk = 0; kk < 32; kk += 16) {
            wmma::fragment<wmma::matrix_a, 16, 16, 16, __half, wmma::row_major> af[2];
            wmma::fragment<wmma::matrix_b, 16, 16, 16, __half, wmma::col_major> bf[2];
#pragma unroll
            for (int i = 0; i < 2; i++)
                wmma::load_matrix_sync(af[i], &Ab[(wm*32 + i*16) * LDA + kk], LDA);
#pragma unroll
            for (int j = 0; j < 2; j++)
                wmma::load_matrix_sync(bf[j], &Bb[(wn*32 + j*16) * LDA + kk], LDA);
#pragma unroll
            for (int i = 0; i < 2; i++)
#pragma unroll
                for (int j = 0; j < 2; j++)
                    wmma::mma_sync(cf[i][j], af[i], bf[j], cf[i][j]);
        }
    }
    __syncthreads();

    const int erow = lane >> 1, ecol0 = (lane & 1) * 8;
    float* wstage = &stage[w * 16 * LDS_];
#pragma unroll
    for (int i = 0; i < 2; i++)
#pragma unroll
        for (int j = 0; j < 2; j++) {
            wmma::store_matrix_sync(wstage, cf[i][j], LDS_, wmma::mem_row_major);
            __syncwarp();
            int r = m0 + wm*32 + i*16 + erow;
            int c = n0 + wn*32 + j*16 + ecol0;
            const float* sp = &wstage[erow * LDS_ + ecol0];
            if (MODE == 0) {
                long off = (long)r * Ncols + c;
                __half2 h[4];
#pragma unroll
                for (int e = 0; e < 4; e++)
                    h[e] = __floats2half2_rn(sp[2*e]   + bias[c + 2*e],
                                             sp[2*e+1] + bias[c + 2*e+1]);
                *reinterpret_cast<uint4*>(outH + off) = *reinterpret_cast<uint4*>(h);
            } else if (MODE == 1) {
                float a = alphas[r / NN];
                long off = (long)r * DD + c;
                __half2 h[4];
#pragma unroll
                for (int e = 0; e < 4; e++) {
                    float v0 = a * (sp[2*e]   + bias[c + 2*e])   + (1.f - a) * Hx[off + 2*e];
                    float v1 = a * (sp[2*e+1] + bias[c + 2*e+1]) + (1.f - a) * Hx[off + 2*e+1];
                    h[e] = __floats2half2_rn(v0, v1);
                }
                *reinterpret_cast<uint4*>(outH + off) = *reinterpret_cast<uint4*>(h);
            } else {
                long off = obase + (long)r * DD + c;
                __half* dst = (which == 0) ? outH : (which == 1) ? outK : outV;
                __half2 h[4];
#pragma unroll
                for (int e = 0; e < 4; e++)
                    h[e] = __floats2half2_rn(sp[2*e], sp[2*e+1]);
                *reinterpret_cast<uint4*>(dst + off) = *reinterpret_cast<uint4*>(h);
            }
            __syncwarp();
        }
}

// ---------------- tiny attention over views: one warp per (n,h) ------------
__global__ __launch_bounds__(256)
void view_attn(const __half* __restrict__ qkv, __half* __restrict__ o)
{
    int gw = blockIdx.x * 8 + (threadIdx.x >> 5);
    if (gw >= NN * NHEADS) return;
    int lane = threadIdx.x & 31;
    int n = gw >> 2;
    int h = gw & 3;

    float2 qf[VV], kf[VV], vf[VV];
#pragma unroll
    for (int l = 0; l < VV; l++) {
        long base = ((long)(l * NN + n)) * (3 * DD) + h * HD + 2 * lane;
        qf[l] = __half22float2(*reinterpret_cast<const __half2*>(qkv + base));
        kf[l] = __half22float2(*reinterpret_cast<const __half2*>(qkv + base + DD));
        vf[l] = __half22float2(*reinterpret_cast<const __half2*>(qkv + base + 2*DD));
    }

    float s[VV][VV];
#pragma unroll
    for (int l = 0; l < VV; l++)
#pragma unroll
        for (int m = 0; m < VV; m++) {
            float p = qf[l].x*kf[m].x + qf[l].y*kf[m].y;
#pragma unroll
            for (int off = 16; off; off >>= 1)
                p += __shfl_xor_sync(0xFFFFFFFFu, p, off);
            s[l][m] = p * 0.125f;
        }

#pragma unroll
    for (int l = 0; l < VV; l++) {
        float mx = fmaxf(fmaxf(s[l][0], s[l][1]), fmaxf(s[l][2], s[l][3]));
        float e0 = __expf(s[l][0]-mx), e1 = __expf(s[l][1]-mx),
              e2 = __expf(s[l][2]-mx), e3 = __expf(s[l][3]-mx);
        float inv = 1.f / (e0+e1+e2+e3);
        float ox = (e0*vf[0].x + e1*vf[1].x + e2*vf[2].x + e3*vf[3].x) * inv;
        float oy = (e0*vf[0].y + e1*vf[1].y + e2*vf[2].y + e3*vf[3].y) * inv;
        long base = ((long)(l * NN + n)) * DD + h * HD + 2 * lane;
        *reinterpret_cast<__half2*>(o + base) = __floats2half2_rn(ox, oy);
    }
}

// ---------------- fast top-32 per off-diagonal (v,q,n) row of C -------------
__global__ __launch_bounds__(256)
void topk_fast(const float* __restrict__ C, int* __restrict__ outIdx)
{
    __shared__ unsigned long long buf[8][CAP];
    const unsigned FULL = 0xFFFFFFFFu;
    int wid = threadIdx.x >> 5, lane = threadIdx.x & 31;
    int gw = blockIdx.x * 8 + wid;
    int pair = gw / NN, n = gw - pair * NN;
    int v = pair / 3, r3 = pair - v * 3;
    int q = r3 + (r3 >= v ? 1 : 0);

    const float* row = C + ((long)(v*4 + q) * NN + n) * (long)NN;
    int* outp = outIdx + ((long)(v*4 + q) * NN + n) * TOPK;
    unsigned long long* wbuf = buf[wid];

    int cnt = 0;
    float thr = 0.95f;
#pragma unroll 1
    for (int att = 0; att < 2; att++) {
        cnt = 0;
#pragma unroll 1
        for (int i = lane; i < NN; i += 32) {
            float x = row[i];
            bool p = x > thr;
            unsigned m = __ballot_sync(FULL, p);
            if (p) {
                int pos = cnt + __popc(m & ((1u << lane) - 1u));
                if (pos < CAP)
                    wbuf[pos] = (((unsigned long long)__float_as_uint(x)) << 32)
                              | (unsigned)(0xFFFFFFFFu - i);
            }
            cnt += __popc(m);
        }
        if (cnt >= TOPK && cnt <= CAP) break;
        thr = 0.90f;
    }

    if (cnt < TOPK || cnt > CAP) {
        unsigned long long prev = 0xFFFFFFFFFFFFFFFFull;
        for (int j = 0; j < TOPK; j++) {
            unsigned long long best = 0;
            for (int i = lane; i < NN; i += 32) {
                unsigned b = __float_as_uint(row[i]);
                unsigned key32 = (b & 0x80000000u) ? ~b : (b | 0x80000000u);
                unsigned long long k =
                    (((unsigned long long)key32) << 32) | (unsigned)(0xFFFFFFFFu - i);
                if (k < prev && k > best) best = k;
            }
#pragma unroll
            for (int off = 16; off; off >>= 1) {
                unsigned long long o = __shfl_xor_sync(FULL, best, off);
                if (o > best) best = o;
            }
            if (lane == 0) outp[j] = (int)(0xFFFFFFFFu - (unsigned)best);
            prev = best;
        }
        return;
    }

    const int SL = CAP / 32;
    unsigned long long c[SL];
#pragma unroll
    for (int k = 0; k < SL; k++) {
        int j = lane + 32 * k;
        c[k] = (j < cnt) ? wbuf[j] : 0ull;
    }
    unsigned long long lmax = 0; int lslot = 0;
#pragma unroll
    for (int k = 0; k < SL; k++) if (c[k] > lmax) { lmax = c[k]; lslot = k; }

#pragma unroll 1
    for (int j = 0; j < TOPK; j++) {
        unsigned long long best = lmax;
#pragma unroll
        for (int off = 16; off; off >>= 1) {
            unsigned long long o = __shfl_xor_sync(FULL, best, off);
            if (o > best) best = o;
        }
        if (lmax == best && best != 0ull) {
            outp[j] = (int)(0xFFFFFFFFu - (unsigned)best);
            c[lslot] = 0ull;
            lmax = 0; lslot = 0;
#pragma unroll
            for (int k = 0; k < SL; k++) if (c[k] > lmax) { lmax = c[k]; lslot = k; }
        }
    }
}

// ---------------- vmean = mean_n(alignedh) @ WV^T (fp32, linearity) --------
// runs on side stream concurrent with hgemm2
__global__ void amean_partial(const __half* __restrict__ alignedh, float* __restrict__ part)
{
    int v = blockIdx.x, chunk = blockIdx.y, t = threadIdx.x;
    float s = 0.f;
    int nbeg = chunk * (NN/8), nend = nbeg + (NN/8);
    for (int n = nbeg; n < nend; n++)
        s += __half2float(alignedh[((long)v * NN + n) * DD + t]);
    part[(v*8 + chunk) * DD + t] = s;
}
__global__ void amean_final(const float* __restrict__ part, float* __restrict__ amean)
{
    int v = blockIdx.x, t = threadIdx.x;
    float s = 0.f;
#pragma unroll
    for (int c = 0; c < 8; c++) s += part[(v*8 + c) * DD + t];
    amean[v * DD + t] = s * (1.0f / NN);
}
__global__ void vmean_gemv(const float* __restrict__ amean,
                           const float* __restrict__ WV, float* __restrict__ vmean)
{
    __shared__ float am[DD];
    int v = blockIdx.x >> 5;
    int grp = blockIdx.x & 31;
    int w = threadIdx.x >> 5, lane = threadIdx.x & 31;
    am[threadIdx.x] = amean[v * DD + threadIdx.x];
    __syncthreads();
    int e = grp * 8 + w;
    const float* row = WV + (long)v * DD * DD + (long)e * DD;
    float s = 0.f;
#pragma unroll
    for (int r = 0; r < 8; r++)
        s += am[r*32 + lane] * row[r*32 + lane];
#pragma unroll
    for (int off = 16; off; off >>= 1)
        s += __shfl_xor_sync(0xFFFFFFFFu, s, off);
    if (lane == 0) vmean[v * DD + e] = s;
}

// ---------------- sparse neighbor attention + final fuse (round-12) --------
#define NBR_SMEM (96*DD*2 + DD*4 + 96*4 + 96*4)

__global__ __launch_bounds__(256, 4)
void nbr_out(const __half* __restrict__ Qh, const __half* __restrict__ Kh,
             const __half* __restrict__ Vh, const float* __restrict__ vmean,
             const int* __restrict__ topk, const __half* __restrict__ alignedh,
             const float* __restrict__ Hin,
             const float* __restrict__ alpha_align, const float* __restrict__ beta,
             float* __restrict__ out)
{
    extern __shared__ __align__(16) char dsm[];
    __half* Vs   = reinterpret_cast<__half*>(dsm);
    float*  Qrow = reinterpret_cast<float*>(dsm + 96*DD*2);
    float*  sdots= reinterpret_cast<float*>(dsm + 96*DD*2 + DD*4);
    int*    srow = reinterpret_cast<int*>(dsm + 96*DD*2 + DD*4 + 96*4);

    int pn = blockIdx.x;
    int p = pn / NN, n = pn % NN;
    int t = threadIdx.x, lane = t & 31, wid = t >> 5;

    long rowOff = (long)pn * DD;
    Qrow[t] = __half2float(Qh[rowOff + t]);
    if (t < 96) {
        int view = t >> 5;
        int q = view + (view >= p ? 1 : 0);
        int idx = topk[(((long)(p*VV + q)) * NN + n) * TOPK + (t & 31)];
        srow[t] = q * NN + idx;
    }
    float acc = vmean[p * DD + t];
    __syncthreads();

#pragma unroll
    for (int r = 0; r < 12; r++) {
        int j = wid * 12 + r;
        cp16(&Vs[j * DD + lane * 8], &Vh[(long)srow[j] * DD + lane * 8]);
    }
    cp_commit();

    float4 qa = *reinterpret_cast<const float4*>(&Qrow[lane*8]);
    float4 qb = *reinterpret_cast<const float4*>(&Qrow[lane*8+4]);
#pragma unroll
    for (int r = 0; r < 12; r += 6) {
        uint4 kv[6];
#pragma unroll
        for (int u = 0; u < 6; u++)
            kv[u] = *reinterpret_cast<const uint4*>(
                Kh + (long)srow[wid*12 + r + u] * DD + lane * 8);
#pragma unroll
        for (int u = 0; u < 6; u++) {
            float2 k0 = __half22float2(*reinterpret_cast<__half2*>(&kv[u].x));
            float2 k1 = __half22float2(*reinterpret_cast<__half2*>(&kv[u].y));
            float2 k2 = __half22float2(*reinterpret_cast<__half2*>(&kv[u].z));
            float2 k3 = __half22float2(*reinterpret_cast<__half2*>(&kv[u].w));
            float psum = qa.x*k0.x + qa.y*k0.y + qa.z*k1.x + qa.w*k1.y
                       + qb.x*k2.x + qb.y*k2.y + qb.z*k3.x + qb.w*k3.y;
#pragma unroll
            for (int off = 16; off; off >>= 1)
                psum += __shfl_xor_sync(0xFFFFFFFFu, psum, off);
            if (lane == 0) sdots[wid*12 + r + u] = psum * 0.0625f;
        }
    }
    __syncthreads();

    if (wid < 3) {
        float x = sdots[wid*32 + lane];
        float mx = x;
#pragma unroll
        for (int off = 16; off; off >>= 1)
            mx = fmaxf(mx, __shfl_xor_sync(0xFFFFFFFFu, mx, off));
        float e = __expf(x - mx);
        float sm = e;
#pragma unroll
        for (int off = 16; off; off >>= 1)
            sm += __shfl_xor_sync(0xFFFFFFFFu, sm, off);
        sdots[wid*32 + lane] = e / sm;
    }
    cp_wait<0>();
    __syncthreads();

    float a1 = 0.f;
#pragma unroll 8
    for (int j = 0; j < 96; j += 2) {
        acc = fmaf(sdots[j],   __half2float(Vs[j*DD + t]),     acc);
        a1  = fmaf(sdots[j+1], __half2float(Vs[(j+1)*DD + t]), a1);
    }
    acc += a1;

    float aa = 1.f / (1.f + __expf(-alpha_align[0]));
    float bb = 1.f / (1.f + __expf(-beta[0]));
    float al = __half2float(alignedh[rowOff + t]);
    float f  = fmaxf(aa * al + (1.f - aa) * acc, 0.f);
    out[rowOff + t] = bb * Hin[rowOff + t] + (1.f - bb) * f;
}

// ---------------- launch ----------------------------------------------------
extern "C" void kernel_launch(void* const* d_in, const int* in_sizes, int n_in,
                              void* d_out, int out_size)
{
    const float* H      = (const float*)d_in[0];
    const float* C      = (const float*)d_in[1];
    const float* WQ     = (const float*)d_in[2];
    const float* WK     = (const float*)d_in[3];
    const float* WV     = (const float*)d_in[4];
    const float* ipw    = (const float*)d_in[5];
    const float* ipb    = (const float*)d_in[6];
    const float* ow     = (const float*)d_in[7];
    const float* ob     = (const float*)d_in[8];
    const float* alphas = (const float*)d_in[9];
    const float* aal    = (const float*)d_in[10];
    const float* bet    = (const float*)d_in[11];
    float* out = (float*)d_out;

    __half *p_Hh, *p_ipwh, *p_owh, *p_WQh, *p_WKh, *p_WVh;
    __half *p_qkvh, *p_oh, *p_alignedh, *p_Qh, *p_Kh, *p_Vh;
    float *p_part, *p_amean, *p_vmean;
    int* p_tk;
    cudaGetSymbolAddress((void**)&p_Hh, g_Hh);
    cudaGetSymbolAddress((void**)&p_ipwh, g_ipwh);
    cudaGetSymbolAddress((void**)&p_owh, g_owh);
    cudaGetSymbolAddress((void**)&p_WQh, g_WQh);
    cudaGetSymbolAddress((void**)&p_WKh, g_WKh);
    cudaGetSymbolAddress((void**)&p_WVh, g_WVh);
    cudaGetSymbolAddress((void**)&p_qkvh, g_qkvh);
    cudaGetSymbolAddress((void**)&p_oh, g_oh);
    cudaGetSymbolAddress((void**)&p_alignedh, g_alignedh);
    cudaGetSymbolAddress((void**)&p_Qh, g_Qh);
    cudaGetSymbolAddress((void**)&p_Kh, g_Kh);
    cudaGetSymbolAddress((void**)&p_Vh, g_Vh);
    cudaGetSymbolAddress((void**)&p_part, g_part);
    cudaGetSymbolAddress((void**)&p_amean, g_amean);
    cudaGetSymbolAddress((void**)&p_vmean, g_vmean);
    cudaGetSymbolAddress((void**)&p_tk, g_topk);

    static cudaStream_t sB = nullptr, sC = nullptr;
    static cudaEvent_t evRoot = nullptr, evB = nullptr, evC = nullptr,
                       evA = nullptr, evV = nullptr;
    if (sB == nullptr) {
        cudaStreamCreateWithFlags(&sB, cudaStreamNonBlocking);
        cudaStreamCreateWithFlags(&sC, cudaStreamNonBlocking);
        cudaEventCreateWithFlags(&evRoot, cudaEventDisableTiming);
        cudaEventCreateWithFlags(&evB, cudaEventDisableTiming);
        cudaEventCreateWithFlags(&evC, cudaEventDisableTiming);
        cudaEventCreateWithFlags(&evA, cudaEventDisableTiming);
        cudaEventCreateWithFlags(&evV, cudaEventDisableTiming);
    }
    cudaFuncSetAttribute(hgemm<0>, cudaFuncAttributeMaxDynamicSharedMemorySize, HG_SMEM);
    cudaFuncSetAttribute(hgemm<1>, cudaFuncAttributeMaxDynamicSharedMemorySize, HG_SMEM);
    cudaFuncSetAttribute(hgemm<2>, cudaFuncAttributeMaxDynamicSharedMemorySize, HG_SMEM);
    cudaFuncSetAttribute(nbr_out, cudaFuncAttributeMaxDynamicSharedMemorySize, NBR_SMEM);

    auto cgrid = [](int n){ return (n/8 + 255) / 256; };

    // fork side streams
    cudaEventRecord(evRoot, 0);
    cudaStreamWaitEvent(sB, evRoot, 0);
    cudaStreamWaitEvent(sC, evRoot, 0);

    // side stream B: top-k over C
    topk_fast<<<(12 * NN) / 8, 256, 0, sB>>>(C, p_tk);
    cudaEventRecord(evB, sB);

    // side stream C: all weight conversions in ONE launch
    f2h_w<<<dim3(cgrid(VV*DD*DD), 5), 256, 0, sC>>>(
        ipw, p_ipwh, 3*DD*DD,
        ow,  p_owh,  DD*DD,
        WQ,  p_WQh,  VV*DD*DD,
        WK,  p_WKh,  VV*DD*DD,
        WV,  p_WVh,  VV*DD*DD);
    cudaEventRecord(evC, sC);

    // main chain
    f2h<<<cgrid(ROWS_TOT*DD), 256>>>(H, p_Hh, ROWS_TOT*DD);
    cudaStreamWaitEvent(0, evC, 0);

    // 1) qkv(f16) = H @ in_proj_w^T + b
    hgemm<0><<<dim3(768/128, ROWS_TOT/64), 256, HG_SMEM>>>(
        p_Hh, p_ipwh, nullptr, nullptr, ipb, nullptr, nullptr,
        p_qkvh, nullptr, nullptr, 3*DD);

    // 2) tiny 4x4 attention over views -> o (fp16)
    view_attn<<<(NN*NHEADS)/8, 256>>>(p_qkvh, p_oh);

    // 3) alignedh = half(a*(o @ out_w^T + b) + (1-a)*H)
    hgemm<1><<<dim3(DD/128, ROWS_TOT/64), 256, HG_SMEM>>>(
        p_oh, p_owh, nullptr, nullptr, ob, H, alphas,
        p_alignedh, nullptr, nullptr, DD);
    cudaEventRecord(evA, 0);

    // side stream C: vmean = mean(alignedh) @ WV^T (concurrent with hgemm2)
    cudaStreamWaitEvent(sC, evA, 0);
    amean_partial<<<dim3(VV, 8), 256, 0, sC>>>(p_alignedh, p_part);
    amean_final<<<VV, 256, 0, sC>>>(p_part, p_amean);
    vmean_gemv<<<VV*32, 256, 0, sC>>>(p_amean, WV, p_vmean);
    cudaEventRecord(evV, sC);

    // 4) fused per-view Qh/Kh/Vh (all fp16)
    hgemm<2><<<dim3(DD/128, NN/64, 12), 256, HG_SMEM>>>(
        p_alignedh, p_WQh, p_WKh, p_WVh, nullptr, nullptr, nullptr,
        p_Qh, p_Kh, p_Vh, DD);

    cudaStreamWaitEvent(0, evB, 0);
    cudaStreamWaitEvent(0, evV, 0);

    // 5) sparse neighbor attention + final relu/fuse
    nbr_out<<<ROWS_TOT, 256, NBR_SMEM>>>(p_Qh, p_Kh, p_Vh, p_vmean, p_tk,
                                         p_alignedh, H, aal, bet, out);
}